// round 5
// baseline (speedup 1.0000x reference)
#include <cuda_runtime.h>
#include <cstdint>
#include <math.h>

// Problem constants
#define BATCH 4
#define T 4096
#define D 512
#define CHK 128
#define NQC 32
#define WKEYS 384               // decay^256/(1-decay) ~ 8e-5 tail: safe
#define MTOT 16384

#define XN (BATCH * T * D)      // 8388608
#define WN (D * D)              // 262144

// Scratch: all GEMM operands pre-rounded to tf32 in memory
__device__ float g_x [XN];
__device__ float g_w [4 * WN];          // Wq, Wk, Wv, Wo rounded
__device__ float g_q [XN];
__device__ float g_k [XN];
__device__ float g_vT[BATCH * D * T];   // V transposed: [b][d][t]
__device__ float g_ws[BATCH * NQC * CHK * WKEYS];
__device__ float g_r [XN];

// ---------------------------------------------------------------------------
// helpers
// ---------------------------------------------------------------------------
__device__ __forceinline__ float tf32r(float x) {
    float r;
    asm("cvt.rna.tf32.f32 %0, %1;" : "=f"(r) : "f"(x));
    return r;
}
__device__ __forceinline__ uint32_t smem_u32(const void* p) {
    uint32_t a;
    asm("{ .reg .u64 t; cvta.to.shared.u64 t, %1; cvt.u32.u64 %0, t; }"
        : "=r"(a) : "l"(p));
    return a;
}
__device__ __forceinline__ void mma8(float* c, const float* a, const float* b) {
    asm volatile(
        "mma.sync.aligned.m16n8k8.row.col.f32.tf32.tf32.f32 "
        "{%0,%1,%2,%3}, {%4,%5,%6,%7}, {%8,%9}, {%0,%1,%2,%3};\n"
        : "+f"(c[0]), "+f"(c[1]), "+f"(c[2]), "+f"(c[3])
        : "r"(__float_as_uint(a[0])), "r"(__float_as_uint(a[1])),
          "r"(__float_as_uint(a[2])), "r"(__float_as_uint(a[3])),
          "r"(__float_as_uint(b[0])), "r"(__float_as_uint(b[1])));
}

#define CP_COMMIT() asm volatile("cp.async.commit_group;" ::: "memory")
#define CP_WAIT(n)  asm volatile("cp.async.wait_group %0;" :: "n"(n) : "memory")

// ---------------------------------------------------------------------------
// Tile config: CTA 128x128, 4 warps (2x2), warp tile 64x64, BK=16.
// 3-stage cp.async pipeline. Smem [row][k] pitch 20 floats (80 B, 16B-aligned
// rows) -> conflict-free fragment LDS. Stage = A(10240 B) + B(10240 B).
// ---------------------------------------------------------------------------
#define PK 20
#define STAGE_B 20480
#define SMEM_BYTES (3 * STAGE_B)

// Issue cp.async for a 128x16 K-contiguous tile (128 threads, 4x16B each).
__device__ __forceinline__ void issue_tile(uint32_t sb, const float* __restrict__ g,
                                           int ld, int tid) {
    const int r0 = tid >> 2;
    const int koff = (tid & 3) * 4;
    const float* src = g + (size_t)r0 * ld + koff;
    uint32_t dst = sb + (uint32_t)r0 * 80u + (uint32_t)(tid & 3) * 16u;
#pragma unroll
    for (int it = 0; it < 4; it++)
        asm volatile("cp.async.cg.shared.global [%0], [%1], 16;"
                     :: "r"(dst + (uint32_t)it * 32u * 80u),
                        "l"(src + (size_t)it * 32 * ld) : "memory");
}

// MMA over one 16-deep stage; A and B both [row][k] pitch-20 (NT form).
__device__ __forceinline__ void mma_tile_nt(
    const float (*As)[PK], const float (*Bs)[PK],
    float acc[4][8][4], int wm, int wn, int g, int c)
{
#pragma unroll
    for (int kb = 0; kb < 16; kb += 8) {
        float a[4][4];
#pragma unroll
        for (int mi = 0; mi < 4; mi++) {
            const float* Ar0 = &As[wm + mi * 16 + g][kb + c];
            const float* Ar8 = &As[wm + mi * 16 + g + 8][kb + c];
            a[mi][0] = Ar0[0];
            a[mi][1] = Ar8[0];
            a[mi][2] = Ar0[4];
            a[mi][3] = Ar8[4];
        }
#pragma unroll
        for (int ni = 0; ni < 8; ni++) {
            float b[2];
            const float* Br = &Bs[wn + ni * 8 + g][kb + c];
            b[0] = Br[0];
            b[1] = Br[4];
#pragma unroll
            for (int mi = 0; mi < 4; mi++)
                mma8(acc[mi][ni], a[mi], b);
        }
    }
}

// Core: acc += A[128,K] * B[128,K]^T, K = nkt*16 floats per... (nkt tiles of 16).
__device__ __forceinline__ void gemm_core(
    const float* __restrict__ A, int lda,
    const float* __restrict__ B, int ldb,
    int nkt, float acc[4][8][4],
    char* dsm, int tid, int wm, int wn, int g, int c)
{
    uint32_t sb = smem_u32(dsm);

    issue_tile(sb, A, lda, tid);
    issue_tile(sb + 10240, B, ldb, tid);
    CP_COMMIT();
    if (nkt > 1) {
        issue_tile(sb + STAGE_B, A + 16, lda, tid);
        issue_tile(sb + STAGE_B + 10240, B + 16, ldb, tid);
        CP_COMMIT();
    }

    for (int it = 0; it < nkt; it++) {
        if (it + 1 < nkt) CP_WAIT(1); else CP_WAIT(0);
        __syncthreads();
        if (it + 2 < nkt) {
            int s2 = (it + 2) % 3;
            issue_tile(sb + s2 * STAGE_B, A + (it + 2) * 16, lda, tid);
            issue_tile(sb + s2 * STAGE_B + 10240, B + (it + 2) * 16, ldb, tid);
            CP_COMMIT();
        }
        int s = it % 3;
        const float (*As)[PK] = (const float (*)[PK])(dsm + s * STAGE_B);
        const float (*Bs)[PK] = (const float (*)[PK])(dsm + s * STAGE_B + 10240);
        mma_tile_nt(As, Bs, acc, wm, wn, g, c);
    }
}

#define GEMM_PROLOGUE()                                  \
    extern __shared__ char dsm[];                        \
    float acc[4][8][4];                                  \
    _Pragma("unroll")                                    \
    for (int i = 0; i < 4; i++)                          \
        _Pragma("unroll")                                \
        for (int j = 0; j < 8; j++)                      \
            _Pragma("unroll")                            \
            for (int q = 0; q < 4; q++) acc[i][j][q] = 0.f; \
    const int tid = threadIdx.x;                         \
    const int warp = tid >> 5, lane = tid & 31;          \
    const int wm = (warp >> 1) * 64, wn = (warp & 1) * 64; \
    const int g = lane >> 2, c = lane & 3;

// ---------------------------------------------------------------------------
// Kernel 0: round x and weights to tf32 in scratch.
// ---------------------------------------------------------------------------
__global__ __launch_bounds__(256) void prep(
    const float* __restrict__ x,
    const float* __restrict__ Wq, const float* __restrict__ Wk,
    const float* __restrict__ Wv, const float* __restrict__ Wo)
{
    int i = (blockIdx.x * 256 + threadIdx.x) * 4;
    int total = XN + 4 * WN;
    for (; i < total; i += gridDim.x * 256 * 4) {
        const float* src;
        float* dst;
        int off;
        if (i < XN) { src = x; dst = g_x; off = i; }
        else {
            int wi = (i - XN) / WN;
            off = (i - XN) - wi * WN;
            src = (wi == 0) ? Wq : (wi == 1) ? Wk : (wi == 2) ? Wv : Wo;
            dst = g_w + wi * WN;
        }
        float4 v = *(const float4*)(src + off);
        *(float4*)(dst + off) = make_float4(tf32r(v.x), tf32r(v.y), tf32r(v.z), tf32r(v.w));
    }
}

// ---------------------------------------------------------------------------
// Kernel 1: QKV. z=0 -> Q, z=1 -> K (row-major), z=2 -> V transposed.
// ---------------------------------------------------------------------------
__global__ __launch_bounds__(128, 3) void qkv_gemm(int dummy)
{
    GEMM_PROLOGUE();
    const int z = blockIdx.z;
    const int row0 = blockIdx.y * 128, col0 = blockIdx.x * 128;
    const float* A = g_x + (size_t)row0 * D;
    const float* B = g_w + (size_t)z * WN + (size_t)col0 * D;

    gemm_core(A, D, B, D, D / 16, acc, dsm, tid, wm, wn, g, c);

    if (z < 2) {
        float* Cp = ((z == 0) ? g_q : g_k) + (size_t)row0 * D + col0;
#pragma unroll
        for (int mi = 0; mi < 4; mi++)
#pragma unroll
            for (int ni = 0; ni < 8; ni++) {
                int row = wm + mi * 16 + g;
                int col = wn + ni * 8 + 2 * c;
                *(float2*)&Cp[(size_t)row * D + col] =
                    make_float2(tf32r(acc[mi][ni][0]), tf32r(acc[mi][ni][1]));
                *(float2*)&Cp[(size_t)(row + 8) * D + col] =
                    make_float2(tf32r(acc[mi][ni][2]), tf32r(acc[mi][ni][3]));
            }
    } else {
        const int b = row0 >> 12;
        const int t0 = row0 & (T - 1);
#pragma unroll
        for (int mi = 0; mi < 4; mi++)
#pragma unroll
            for (int ni = 0; ni < 8; ni++) {
                int t = t0 + wm + mi * 16 + g;
                int col = col0 + wn + ni * 8 + 2 * c;
                float* base0 = g_vT + ((size_t)b * D + col) * T;
                float* base1 = base0 + T;
                base0[t]     = tf32r(acc[mi][ni][0]);
                base1[t]     = tf32r(acc[mi][ni][1]);
                base0[t + 8] = tf32r(acc[mi][ni][2]);
                base1[t + 8] = tf32r(acc[mi][ni][3]);
            }
    }
}

// ---------------------------------------------------------------------------
// Kernel 2: banded scores + decay weights -> g_ws (tf32-rounded).
// ---------------------------------------------------------------------------
__global__ __launch_bounds__(128, 3) void scores_gemm(const float* __restrict__ decay_logit)
{
    const int bid = blockIdx.y;
    const int b = bid >> 5, qc = bid & 31;
    const int col0 = blockIdx.x * 128;
    const int kvalid = T - qc * CHK;
    if (col0 >= kvalid) return;   // out-of-range key tile; WS region never read

    GEMM_PROLOGUE();
    const float* A = g_q + (size_t)(b * T + qc * CHK) * D;
    const float* B = g_k + (size_t)(b * T + qc * CHK + col0) * D;

    gemm_core(A, D, B, D, D / 16, acc, dsm, tid, wm, wn, g, c);

    const float dl = *decay_logit;
    const float decay = 1.f / (1.f + expf(-dl));
    const float l2d = log2f(decay);
    float* WS = g_ws + (size_t)(b * NQC + qc) * CHK * WKEYS;

#pragma unroll
    for (int mi = 0; mi < 4; mi++)
#pragma unroll
        for (int ni = 0; ni < 8; ni++) {
#pragma unroll
            for (int half = 0; half < 2; half++) {
                int ti = wm + mi * 16 + g + half * 8;
                float2 o;
#pragma unroll
                for (int e = 0; e < 2; e++) {
                    int jj = col0 + wn + ni * 8 + 2 * c + e;
                    int diff = jj - ti;
                    float w = (diff > 0) ? exp2f((float)(diff - 1) * l2d) : 0.f;
                    float v = tf32r(acc[mi][ni][half * 2 + e] * w);
                    if (e == 0) o.x = v; else o.y = v;
                }
                int jj0 = col0 + wn + ni * 8 + 2 * c;
                *(float2*)&WS[(size_t)ti * WKEYS + jj0] = o;
            }
        }
}

// ---------------------------------------------------------------------------
// Kernel 3: retrieved = WS @ V_window (NT against g_vT), tf32-rounded store.
// ---------------------------------------------------------------------------
__global__ __launch_bounds__(128, 3) void retrv_gemm(int dummy)
{
    GEMM_PROLOGUE();
    const int bid = blockIdx.y;
    const int b = bid >> 5, qc = bid & 31;
    const int col0 = blockIdx.x * 128;
    const int kvalid = T - qc * CHK;
    const int keff = (kvalid < WKEYS) ? kvalid : WKEYS;
    const int nkt = keff / 16;    // 8..24 tiles of 16

    const float* A = g_ws + (size_t)(b * NQC + qc) * CHK * WKEYS;
    const float* B = g_vT + ((size_t)b * D + col0) * T + qc * CHK;

    gemm_core(A, WKEYS, B, T, nkt, acc, dsm, tid, wm, wn, g, c);

    float* Cp = g_r + (size_t)(b * T + qc * CHK) * D + col0;
#pragma unroll
    for (int mi = 0; mi < 4; mi++)
#pragma unroll
        for (int ni = 0; ni < 8; ni++) {
            int row = wm + mi * 16 + g;
            int col = wn + ni * 8 + 2 * c;
            *(float2*)&Cp[(size_t)row * D + col] =
                make_float2(tf32r(acc[mi][ni][0]), tf32r(acc[mi][ni][1]));
            *(float2*)&Cp[(size_t)(row + 8) * D + col] =
                make_float2(tf32r(acc[mi][ni][2]), tf32r(acc[mi][ni][3]));
        }
}

// ---------------------------------------------------------------------------
// Kernel 4: out = (R @ Wo^T) * out_scale  (full fp32 store)
// ---------------------------------------------------------------------------
__global__ __launch_bounds__(128, 3) void out_gemm(
    const float* __restrict__ out_scale,
    float* __restrict__ out)
{
    GEMM_PROLOGUE();
    const int row0 = blockIdx.y * 128, col0 = blockIdx.x * 128;
    const float* A = g_r + (size_t)row0 * D;
    const float* B = g_w + 3 * WN + (size_t)col0 * D;

    gemm_core(A, D, B, D, D / 16, acc, dsm, tid, wm, wn, g, c);

    const float sc = *out_scale;
    float* Cp = out + (size_t)row0 * D + col0;
#pragma unroll
    for (int mi = 0; mi < 4; mi++)
#pragma unroll
        for (int ni = 0; ni < 8; ni++) {
            int row = wm + mi * 16 + g;
            int col = wn + ni * 8 + 2 * c;
            *(float2*)&Cp[(size_t)row * D + col] =
                make_float2(acc[mi][ni][0] * sc, acc[mi][ni][1] * sc);
            *(float2*)&Cp[(size_t)(row + 8) * D + col] =
                make_float2(acc[mi][ni][2] * sc, acc[mi][ni][3] * sc);
        }
}

// ---------------------------------------------------------------------------
extern "C" void kernel_launch(void* const* d_in, const int* in_sizes, int n_in,
                              void* d_out, int out_size)
{
    const float* x  = (const float*)d_in[0];
    const float* Wq = (const float*)d_in[1];
    const float* Wk = (const float*)d_in[2];
    const float* Wv = (const float*)d_in[3];
    const float* Wo = (const float*)d_in[4];
    const float* dl = (const float*)d_in[5];
    const float* os = (const float*)d_in[6];
    float* out = (float*)d_out;

    cudaFuncSetAttribute(qkv_gemm,    cudaFuncAttributeMaxDynamicSharedMemorySize, SMEM_BYTES);
    cudaFuncSetAttribute(scores_gemm, cudaFuncAttributeMaxDynamicSharedMemorySize, SMEM_BYTES);
    cudaFuncSetAttribute(retrv_gemm,  cudaFuncAttributeMaxDynamicSharedMemorySize, SMEM_BYTES);
    cudaFuncSetAttribute(out_gemm,    cudaFuncAttributeMaxDynamicSharedMemorySize, SMEM_BYTES);

    prep<<<512, 256>>>(x, Wq, Wk, Wv, Wo);
    dim3 blk(128);
    qkv_gemm   <<<dim3(4, MTOT / 128, 3), blk, SMEM_BYTES>>>(0);
    scores_gemm<<<dim3(WKEYS / 128, BATCH * NQC), blk, SMEM_BYTES>>>(dl);
    retrv_gemm <<<dim3(4, BATCH * NQC), blk, SMEM_BYTES>>>(0);
    out_gemm   <<<dim3(4, MTOT / 128), blk, SMEM_BYTES>>>(os, out);
}